// round 16
// baseline (speedup 1.0000x reference)
#include <cuda_runtime.h>
#include <cuda_fp16.h>
#include <cuda_bf16.h>
#include <math.h>

#define NN 50000
#define NE 600000
#define NG 256
#define BN_EPS 1e-5f
#define SB 256
#define SNB ((NN + SB - 1) / SB)

// ---------------- scratch (device globals) ----------------------------------
__device__ float  g_agg[(size_t)NN * 256];
__device__ unsigned short g_h0h[(size_t)NN * 64];
__device__ unsigned short g_h0l[(size_t)NN * 64];
__device__ unsigned short g_aggh[(size_t)NN * 256];
__device__ unsigned short g_aggl[(size_t)NN * 256];
__device__ unsigned short g_w0h[2 * 64 * 256], g_w0l[2 * 64 * 256];
__device__ unsigned short g_w1h[2 * 256 * 256], g_w1l[2 * 256 * 256];
__device__ __half g_xl[(size_t)NN * 256];
__device__ __half g_xr[(size_t)NN * 256];
__device__ __half g_em[(size_t)NE * 256];
__device__ int2   g_edge2[NE];          // (src, eidx) per CSR slot
__device__ int    g_deg[NN];
__device__ int    g_rowptr[NN + 1];
__device__ int    g_cursor[NN];
__device__ int    g_bsum[SB];
__device__ int    g_boff[SB];
__device__ double g_bns[512];
__device__ float  g_scale[256];
__device__ float  g_shift[256];
__device__ float  g_pool[NG * 64];
__device__ float  g_cnt[NG];

// ---------------- PTX helpers -------------------------------------------------
__device__ __forceinline__ void mma16816(float* c, const unsigned* a, unsigned b0, unsigned b1) {
    asm volatile(
        "mma.sync.aligned.m16n8k16.row.col.f32.bf16.bf16.f32 "
        "{%0,%1,%2,%3},{%4,%5,%6,%7},{%8,%9},{%0,%1,%2,%3};"
        : "+f"(c[0]), "+f"(c[1]), "+f"(c[2]), "+f"(c[3])
        : "r"(a[0]), "r"(a[1]), "r"(a[2]), "r"(a[3]), "r"(b0), "r"(b1));
}
__device__ __forceinline__ void mma16816f16(float* c, const unsigned* a, unsigned b0, unsigned b1) {
    asm volatile(
        "mma.sync.aligned.m16n8k16.row.col.f32.f16.f16.f32 "
        "{%0,%1,%2,%3},{%4,%5,%6,%7},{%8,%9},{%0,%1,%2,%3};"
        : "+f"(c[0]), "+f"(c[1]), "+f"(c[2]), "+f"(c[3])
        : "r"(a[0]), "r"(a[1]), "r"(a[2]), "r"(a[3]), "r"(b0), "r"(b1));
}
__device__ __forceinline__ void ldsm4(unsigned* r, unsigned addr) {
    asm volatile("ldmatrix.sync.aligned.m8n8.x4.shared.b16 {%0,%1,%2,%3}, [%4];"
                 : "=r"(r[0]), "=r"(r[1]), "=r"(r[2]), "=r"(r[3]) : "r"(addr));
}
__device__ __forceinline__ void ldsm4t(unsigned* r, unsigned addr) {
    asm volatile("ldmatrix.sync.aligned.m8n8.x4.trans.shared.b16 {%0,%1,%2,%3}, [%4];"
                 : "=r"(r[0]), "=r"(r[1]), "=r"(r[2]), "=r"(r[3]) : "r"(addr));
}
__device__ __forceinline__ void split_bf16(float v, unsigned short& h, unsigned short& l) {
    __nv_bfloat16 hb = __float2bfloat16(v);
    h = __bfloat16_as_ushort(hb);
    l = __bfloat16_as_ushort(__float2bfloat16(v - __bfloat162float(hb)));
}
__device__ __forceinline__ uint4 ldcs_u4(const void* p) {
    uint4 v;
    asm volatile("ld.global.cs.v4.u32 {%0,%1,%2,%3}, [%4];"
                 : "=r"(v.x), "=r"(v.y), "=r"(v.z), "=r"(v.w) : "l"(p));
    return v;
}
__device__ __forceinline__ void stcs_u4(void* p, uint4 v) {
    asm volatile("st.global.cs.v4.u32 [%0], {%1,%2,%3,%4};"
                 :: "l"(p), "r"(v.x), "r"(v.y), "r"(v.z), "r"(v.w) : "memory");
}

// ---------------- presplit helpers ---------------------------------------------
__global__ void presplit_w(const float* __restrict__ W0, const float* __restrict__ W1,
                           unsigned short* __restrict__ outh, unsigned short* __restrict__ outl,
                           int n0, int ntot) {
    int i = blockIdx.x * blockDim.x + threadIdx.x;
    if (i >= ntot) return;
    float v = (i < n0) ? W0[i] : W1[i - n0];
    unsigned short h, l;
    split_bf16(v, h, l);
    outh[i] = h;
    outl[i] = l;
}

__global__ void presplit_a(const float* __restrict__ A, const float* __restrict__ scale,
                           const float* __restrict__ shift, unsigned short* __restrict__ outh,
                           unsigned short* __restrict__ outl, int total) {
    int i = blockIdx.x * blockDim.x + threadIdx.x;
    if (i >= total) return;
    int c = i & 255;
    float v = fmaxf(A[i] * scale[c] + shift[c], 0.f);
    unsigned short h, l;
    split_bf16(v, h, l);
    outh[i] = h;
    outl[i] = l;
}

// ---------------- slim em GEMM: C[M,256](fp16) = A[M,16] @ B[16,256] ----------
__global__ __launch_bounds__(256) void em_gemm(const float* __restrict__ A,
                                               const float* __restrict__ B,
                                               __half* __restrict__ C, int M) {
    __shared__ __align__(16) unsigned SMU[5120];
    __half* As = (__half*)SMU;
    __half* Bs = (__half*)(SMU + 2048);
    const int t = threadIdx.x;
    const int lane = t & 31, wid = t >> 5;
    const int m0 = blockIdx.y * 128, n0 = blockIdx.x * 64;
    const int wm = (wid & 3) * 32, wn = (wid >> 2) * 32;
    const int N = 256;

    {
        int row = t >> 1, kc = (t & 1) * 8;
        float4 v0 = make_float4(0.f, 0.f, 0.f, 0.f), v1 = v0;
        if (m0 + row < M) {
            const float* p = A + (size_t)(m0 + row) * 16 + kc;
            v0 = *(const float4*)p;
            v1 = *(const float4*)(p + 4);
        }
        __half2 h0 = __floats2half2_rn(v0.x, v0.y);
        __half2 h1 = __floats2half2_rn(v0.z, v0.w);
        __half2 h2 = __floats2half2_rn(v1.x, v1.y);
        __half2 h3 = __floats2half2_rn(v1.z, v1.w);
        int chunk = kc >> 3;
        int pos = row * 32 + ((chunk ^ ((row >> 1) & 3)) << 3);
        *(uint4*)&As[pos] = make_uint4(*(unsigned*)&h0, *(unsigned*)&h1,
                                       *(unsigned*)&h2, *(unsigned*)&h3);
    }
    {
        int k = t >> 4, nc = (t & 15) * 4;
        float4 v = *(const float4*)(B + (size_t)k * N + n0 + nc);
        __half2 h0 = __floats2half2_rn(v.x, v.y);
        __half2 h1 = __floats2half2_rn(v.z, v.w);
        int chunk = nc >> 3;
        int pos = k * 64 + (((chunk ^ (k & 7)) << 3) | (nc & 7));
        *(uint2*)&Bs[pos] = make_uint2(*(unsigned*)&h0, *(unsigned*)&h1);
    }
    __syncthreads();

    float acc[2][4][4];
#pragma unroll
    for (int i = 0; i < 2; i++)
#pragma unroll
        for (int j = 0; j < 4; j++)
#pragma unroll
            for (int q = 0; q < 4; q++) acc[i][j][q] = 0.f;

    const unsigned as_base = (unsigned)__cvta_generic_to_shared(As);
    const unsigned bs_base = (unsigned)__cvta_generic_to_shared(Bs);

    unsigned af[2][4];
#pragma unroll
    for (int mt = 0; mt < 2; mt++) {
        int row = wm + mt * 16 + (lane & 15);
        int chunk = lane >> 4;
        unsigned off = (unsigned)(row * 32 + ((chunk ^ ((row >> 1) & 3)) << 3)) * 2u;
        ldsm4(af[mt], as_base + off);
    }
    unsigned bf[2][4];
    {
        int g = lane >> 3, r = lane & 7;
        int bk = ((g & 1) << 3) + r;
#pragma unroll
        for (int np = 0; np < 2; np++) {
            int n = wn + np * 16 + ((g >> 1) << 3);
            int chunk = n >> 3;
            unsigned off = (unsigned)(bk * 64 + ((chunk ^ (bk & 7)) << 3)) * 2u;
            ldsm4t(bf[np], bs_base + off);
        }
    }
#pragma unroll
    for (int mt = 0; mt < 2; mt++)
#pragma unroll
        for (int nt = 0; nt < 4; nt++) {
            int np = nt >> 1, hf = (nt & 1) << 1;
            mma16816f16(acc[mt][nt], af[mt], bf[np][hf], bf[np][hf + 1]);
        }
    __syncthreads();

    const int r_ = lane >> 2, c2 = (lane & 3) * 2;
    unsigned* stage = SMU + wid * 640;
#pragma unroll
    for (int mt = 0; mt < 2; mt++)
#pragma unroll
        for (int nt = 0; nt < 4; nt++) {
            int colp = nt * 4 + (c2 >> 1);
#pragma unroll
            for (int half = 0; half < 2; half++) {
                int row = mt * 16 + half * 8 + r_;
                __half2 hv = __floats2half2_rn(acc[mt][nt][half * 2],
                                               acc[mt][nt][half * 2 + 1]);
                stage[row * 20 + colp] = *reinterpret_cast<unsigned*>(&hv);
            }
        }
    __syncwarp();
#pragma unroll
    for (int rg = 0; rg < 4; rg++) {
        int row = rg * 8 + (lane >> 2);
        int grow = m0 + wm + row;
        if (grow < M) {
            uint4 v = *(uint4*)&stage[row * 20 + (lane & 3) * 4];
            stcs_u4(C + (size_t)grow * N + n0 + wn + (lane & 3) * 8, v);
        }
    }
}

// ---------------- pre-split bf16 dual-B GEMM, double-buffered -------------------
// C(fp16) = A@B + bias, A as (Ah,Al) bf16 [M,K], B as bf16 [K,N] (h/l pair).
// Block 128x64, 256 threads, BK=32, register prefetch + 2-stage smem.
__global__ __launch_bounds__(256) void tgemm_pre(
    const unsigned short* __restrict__ Ah, const unsigned short* __restrict__ Al,
    const unsigned short* __restrict__ B0h, const unsigned short* __restrict__ B0l,
    const unsigned short* __restrict__ B1h, const unsigned short* __restrict__ B1l,
    const float* __restrict__ bias0, const float* __restrict__ bias1,
    __half* __restrict__ C0, __half* __restrict__ C1, int M, int N, int K) {
    __shared__ __align__(16) unsigned short SM[24576];   // 2 stages x 24KB
    const int SBUF = 12288;                              // halfs per stage
    const int t = threadIdx.x;
    const int lane = t & 31, wid = t >> 5;
    const int nb = N >> 6;
    const int bx = blockIdx.x;
    const bool second = bx >= nb;
    const unsigned short* Bh = second ? B1h : B0h;
    const unsigned short* Bl = second ? B1l : B0l;
    const float* bias = second ? bias1 : bias0;
    __half* C = second ? C1 : C0;
    const int m0 = blockIdx.y * 128;
    const int n0 = (second ? bx - nb : bx) * 64;
    const int wm = (wid & 3) * 32, wn = (wid >> 2) * 32;

    float acc[2][4][4];
#pragma unroll
    for (int i = 0; i < 2; i++)
#pragma unroll
        for (int j = 0; j < 4; j++)
#pragma unroll
            for (int q = 0; q < 4; q++) acc[i][j][q] = 0.f;

    const unsigned sm_base = (unsigned)__cvta_generic_to_shared(SM);
    // per-stage half offsets: Ash=0, Asl=4096, Bsh=8192, Bsl=10240

    // A-store position (same every tile)
    const int a_row = t >> 2, a_kc8 = (t & 3) << 3;
    const int a_pos0 = a_row * 32 + (((a_kc8 >> 3) ^ ((a_row >> 1) & 3)) << 3);
    const int a_row2 = (t + 256) >> 2, a_kc82 = ((t + 256) & 3) << 3;
    const int a_pos1 = a_row2 * 32 + (((a_kc82 >> 3) ^ ((a_row2 >> 1) & 3)) << 3);
    const int b_k = t >> 3, b_nc8 = (t & 7) << 3;
    const int b_pos = b_k * 64 + (((b_nc8 >> 3) ^ (b_k & 7)) << 3);

    uint4 pah[2], pal[2], pbh, pbl;
    // prefetch tile 0
    {
        pah[0] = make_uint4(0, 0, 0, 0); pal[0] = pah[0];
        pah[1] = pah[0]; pal[1] = pah[0];
        if (m0 + a_row < M) {
            pah[0] = *(const uint4*)(Ah + (size_t)(m0 + a_row) * K + a_kc8);
            pal[0] = *(const uint4*)(Al + (size_t)(m0 + a_row) * K + a_kc8);
        }
        if (m0 + a_row2 < M) {
            pah[1] = *(const uint4*)(Ah + (size_t)(m0 + a_row2) * K + a_kc82);
            pal[1] = *(const uint4*)(Al + (size_t)(m0 + a_row2) * K + a_kc82);
        }
        pbh = *(const uint4*)(Bh + (size_t)b_k * N + n0 + b_nc8);
        pbl = *(const uint4*)(Bl + (size_t)b_k * N + n0 + b_nc8);
    }
    // store tile 0 -> stage 0
    {
        unsigned short* Ash = SM;
        unsigned short* Asl = SM + 4096;
        unsigned short* Bsh = SM + 8192;
        unsigned short* Bsl = SM + 10240;
        *(uint4*)&Ash[a_pos0] = pah[0];
        *(uint4*)&Asl[a_pos0] = pal[0];
        *(uint4*)&Ash[a_pos1] = pah[1];
        *(uint4*)&Asl[a_pos1] = pal[1];
        *(uint4*)&Bsh[b_pos] = pbh;
        *(uint4*)&Bsl[b_pos] = pbl;
    }
    __syncthreads();

    for (int k0 = 0; k0 < K; k0 += 32) {
        const int cur = (k0 >> 5) & 1;
        const unsigned st_base = sm_base + (unsigned)(cur * SBUF) * 2u;
        const int kn = k0 + 32;
        // prefetch next tile into regs (overlaps MMA)
        if (kn < K) {
            pah[0] = make_uint4(0, 0, 0, 0); pal[0] = pah[0];
            pah[1] = pah[0]; pal[1] = pah[0];
            if (m0 + a_row < M) {
                pah[0] = *(const uint4*)(Ah + (size_t)(m0 + a_row) * K + kn + a_kc8);
                pal[0] = *(const uint4*)(Al + (size_t)(m0 + a_row) * K + kn + a_kc8);
            }
            if (m0 + a_row2 < M) {
                pah[1] = *(const uint4*)(Ah + (size_t)(m0 + a_row2) * K + kn + a_kc82);
                pal[1] = *(const uint4*)(Al + (size_t)(m0 + a_row2) * K + kn + a_kc82);
            }
            pbh = *(const uint4*)(Bh + (size_t)(kn + b_k) * N + n0 + b_nc8);
            pbl = *(const uint4*)(Bl + (size_t)(kn + b_k) * N + n0 + b_nc8);
        }

        // MMA on current stage
#pragma unroll
        for (int kk = 0; kk < 32; kk += 16) {
            unsigned afh[2][4], afl[2][4];
#pragma unroll
            for (int mt = 0; mt < 2; mt++) {
                int row = wm + mt * 16 + (lane & 15);
                int chunk = (kk >> 3) + (lane >> 4);
                unsigned off = (unsigned)(row * 32 + ((chunk ^ ((row >> 1) & 3)) << 3)) * 2u;
                ldsm4(afh[mt], st_base + off);
                ldsm4(afl[mt], st_base + 8192u + off);
            }
            unsigned bfh[2][4], bfl[2][4];
            int g = lane >> 3, r = lane & 7;
            int bk = kk + ((g & 1) << 3) + r;
#pragma unroll
            for (int np = 0; np < 2; np++) {
                int n = wn + np * 16 + ((g >> 1) << 3);
                int chunk = n >> 3;
                unsigned off = (unsigned)(bk * 64 + ((chunk ^ (bk & 7)) << 3)) * 2u;
                ldsm4t(bfh[np], st_base + 16384u + off);
                ldsm4t(bfl[np], st_base + 20480u + off);
            }
#pragma unroll
            for (int mt = 0; mt < 2; mt++)
#pragma unroll
                for (int nt = 0; nt < 4; nt++) {
                    int np = nt >> 1, hf = (nt & 1) << 1;
                    mma16816(acc[mt][nt], afh[mt], bfh[np][hf], bfh[np][hf + 1]);
                    mma16816(acc[mt][nt], afh[mt], bfl[np][hf], bfl[np][hf + 1]);
                    mma16816(acc[mt][nt], afl[mt], bfh[np][hf], bfh[np][hf + 1]);
                }
        }

        // store next tile to other stage (no conflict with current reads)
        if (kn < K) {
            unsigned short* buf = SM + (cur ^ 1) * SBUF;
            *(uint4*)&buf[a_pos0] = pah[0];
            *(uint4*)&buf[4096 + a_pos0] = pal[0];
            *(uint4*)&buf[a_pos1] = pah[1];
            *(uint4*)&buf[4096 + a_pos1] = pal[1];
            *(uint4*)&buf[8192 + b_pos] = pbh;
            *(uint4*)&buf[10240 + b_pos] = pbl;
        }
        __syncthreads();
    }

    // staged fp16 epilogue (reuses SM stage 0)
    const int r_ = lane >> 2, c2 = (lane & 3) * 2;
    unsigned* stage = (unsigned*)SM + wid * 640;
#pragma unroll
    for (int mt = 0; mt < 2; mt++)
#pragma unroll
        for (int nt = 0; nt < 4; nt++) {
            int colp = nt * 4 + (c2 >> 1);
            int col = n0 + wn + nt * 8 + c2;
#pragma unroll
            for (int half = 0; half < 2; half++) {
                int row = mt * 16 + half * 8 + r_;
                float v0 = acc[mt][nt][half * 2] + bias[col];
                float v1 = acc[mt][nt][half * 2 + 1] + bias[col + 1];
                __half2 hv = __floats2half2_rn(v0, v1);
                stage[row * 20 + colp] = *reinterpret_cast<unsigned*>(&hv);
            }
        }
    __syncwarp();
#pragma unroll
    for (int rg = 0; rg < 4; rg++) {
        int row = rg * 8 + (lane >> 2);
        int grow = m0 + wm + row;
        if (grow < M) {
            uint4 v = *(uint4*)&stage[row * 20 + (lane & 3) * 4];
            stcs_u4(C + (size_t)grow * N + n0 + wn + (lane & 3) * 8, v);
        }
    }
}

// ---------------- projection GEMM (fp32 in, bf16 hi/lo split out) ---------------
__global__ __launch_bounds__(256) void proj_gemm(const float* __restrict__ A,
                                                 const float* __restrict__ B,
                                                 const float* __restrict__ bias,
                                                 unsigned short* __restrict__ Ch,
                                                 unsigned short* __restrict__ Cl,
                                                 int M, int N, int K) {
    __shared__ __align__(16) unsigned short SM[12288];
    unsigned short* Ash = SM;
    unsigned short* Asl = SM + 4096;
    unsigned short* Bsh = SM + 8192;
    unsigned short* Bsl = SM + 10240;
    const int t = threadIdx.x;
    const int lane = t & 31, wid = t >> 5;
    const int m0 = blockIdx.y * 128;
    const int n0 = blockIdx.x * 64;
    const int wm = (wid & 3) * 32, wn = (wid >> 2) * 32;

    float acc[2][4][4];
#pragma unroll
    for (int i = 0; i < 2; i++)
#pragma unroll
        for (int j = 0; j < 4; j++)
#pragma unroll
            for (int q = 0; q < 4; q++) acc[i][j][q] = 0.f;

    const unsigned ah_base = (unsigned)__cvta_generic_to_shared(Ash);
    const unsigned al_base = (unsigned)__cvta_generic_to_shared(Asl);
    const unsigned bh_base = (unsigned)__cvta_generic_to_shared(Bsh);
    const unsigned bl_base = (unsigned)__cvta_generic_to_shared(Bsl);

    for (int k0 = 0; k0 < K; k0 += 32) {
#pragma unroll
        for (int i = 0; i < 4; i++) {
            int fidx = t + i * 256;
            int row = fidx >> 3, kc = (fidx & 7) << 2;
            float4 v = make_float4(0.f, 0.f, 0.f, 0.f);
            if (m0 + row < M) v = *(const float4*)(A + (size_t)(m0 + row) * K + k0 + kc);
            unsigned short h[4], l[4];
            split_bf16(v.x, h[0], l[0]); split_bf16(v.y, h[1], l[1]);
            split_bf16(v.z, h[2], l[2]); split_bf16(v.w, h[3], l[3]);
            int chunk = kc >> 3;
            int pos = row * 32 + (((chunk ^ ((row >> 1) & 3)) << 3) | (kc & 7));
            *(uint2*)&Ash[pos] = make_uint2((unsigned)h[0] | ((unsigned)h[1] << 16),
                                            (unsigned)h[2] | ((unsigned)h[3] << 16));
            *(uint2*)&Asl[pos] = make_uint2((unsigned)l[0] | ((unsigned)l[1] << 16),
                                            (unsigned)l[2] | ((unsigned)l[3] << 16));
        }
#pragma unroll
        for (int i = 0; i < 2; i++) {
            int fidx = t + i * 256;
            int k = fidx >> 4, nc = (fidx & 15) << 2;
            float4 v = *(const float4*)(B + (size_t)(k0 + k) * N + n0 + nc);
            unsigned short h[4], l[4];
            split_bf16(v.x, h[0], l[0]); split_bf16(v.y, h[1], l[1]);
            split_bf16(v.z, h[2], l[2]); split_bf16(v.w, h[3], l[3]);
            int chunk = nc >> 3;
            int pos = k * 64 + (((chunk ^ (k & 7)) << 3) | (nc & 7));
            *(uint2*)&Bsh[pos] = make_uint2((unsigned)h[0] | ((unsigned)h[1] << 16),
                                            (unsigned)h[2] | ((unsigned)h[3] << 16));
            *(uint2*)&Bsl[pos] = make_uint2((unsigned)l[0] | ((unsigned)l[1] << 16),
                                            (unsigned)l[2] | ((unsigned)l[3] << 16));
        }
        __syncthreads();

#pragma unroll
        for (int kk = 0; kk < 32; kk += 16) {
            unsigned afh[2][4], afl[2][4];
#pragma unroll
            for (int mt = 0; mt < 2; mt++) {
                int row = wm + mt * 16 + (lane & 15);
                int chunk = (kk >> 3) + (lane >> 4);
                unsigned off = (unsigned)(row * 32 + ((chunk ^ ((row >> 1) & 3)) << 3)) * 2u;
                ldsm4(afh[mt], ah_base + off);
                ldsm4(afl[mt], al_base + off);
            }
            unsigned bfh[2][4], bfl[2][4];
            int g = lane >> 3, r = lane & 7;
            int bk = kk + ((g & 1) << 3) + r;
#pragma unroll
            for (int np = 0; np < 2; np++) {
                int n = wn + np * 16 + ((g >> 1) << 3);
                int chunk = n >> 3;
                unsigned off = (unsigned)(bk * 64 + ((chunk ^ (bk & 7)) << 3)) * 2u;
                ldsm4t(bfh[np], bh_base + off);
                ldsm4t(bfl[np], bl_base + off);
            }
#pragma unroll
            for (int mt = 0; mt < 2; mt++)
#pragma unroll
                for (int nt = 0; nt < 4; nt++) {
                    int np = nt >> 1, hf = (nt & 1) << 1;
                    mma16816(acc[mt][nt], afh[mt], bfh[np][hf], bfh[np][hf + 1]);
                    mma16816(acc[mt][nt], afh[mt], bfl[np][hf], bfl[np][hf + 1]);
                    mma16816(acc[mt][nt], afl[mt], bfh[np][hf], bfh[np][hf + 1]);
                }
        }
        __syncthreads();
    }

    const int r_ = lane >> 2, c2 = (lane & 3) * 2;
#pragma unroll
    for (int mt = 0; mt < 2; mt++)
#pragma unroll
        for (int nt = 0; nt < 4; nt++) {
            int col = n0 + wn + nt * 8 + c2;
#pragma unroll
            for (int half = 0; half < 2; half++) {
                int row = m0 + wm + mt * 16 + r_ + half * 8;
                if (row >= M) continue;
                float v0 = fmaxf(acc[mt][nt][half * 2] + bias[col], 0.f);
                float v1 = fmaxf(acc[mt][nt][half * 2 + 1] + bias[col + 1], 0.f);
                unsigned short h0_, l0_, h1_, l1_;
                split_bf16(v0, h0_, l0_);
                split_bf16(v1, h1_, l1_);
                size_t base = (size_t)row * N + col;
                Ch[base] = h0_; Ch[base + 1] = h1_;
                Cl[base] = l0_; Cl[base + 1] = l1_;
            }
        }
}

// ---------------- CSR build --------------------------------------------------
__global__ void hist_kernel(const int* __restrict__ dst, int* __restrict__ deg) {
    int e = blockIdx.x * blockDim.x + threadIdx.x;
    if (e < NE) atomicAdd(&deg[dst[e]], 1);
}

__global__ void scan_block_sums(const int* __restrict__ deg, int* __restrict__ bsum) {
    __shared__ int sh[SB];
    int i = blockIdx.x * SB + threadIdx.x;
    sh[threadIdx.x] = (i < NN) ? deg[i] : 0;
    __syncthreads();
    for (int o = SB / 2; o > 0; o >>= 1) {
        if (threadIdx.x < o) sh[threadIdx.x] += sh[threadIdx.x + o];
        __syncthreads();
    }
    if (threadIdx.x == 0) bsum[blockIdx.x] = sh[0];
}

__global__ void scan_offsets(const int* __restrict__ bsum, int* __restrict__ boff, int nb) {
    __shared__ int sh[SB];
    int t = threadIdx.x;
    int mine = (t < nb) ? bsum[t] : 0;
    sh[t] = mine;
    __syncthreads();
    for (int o = 1; o < SB; o <<= 1) {
        int v = (t >= o) ? sh[t - o] : 0;
        __syncthreads();
        sh[t] += v;
        __syncthreads();
    }
    if (t < nb) boff[t] = sh[t] - mine;
}

__global__ void scan_final(const int* __restrict__ deg, const int* __restrict__ boff,
                           int* __restrict__ rowptr, int* __restrict__ cursor) {
    __shared__ int sh[SB];
    int t = threadIdx.x;
    int i = blockIdx.x * SB + t;
    int d = (i < NN) ? deg[i] : 0;
    sh[t] = d;
    __syncthreads();
    for (int o = 1; o < SB; o <<= 1) {
        int v = (t >= o) ? sh[t - o] : 0;
        __syncthreads();
        sh[t] += v;
        __syncthreads();
    }
    int excl = boff[blockIdx.x] + sh[t] - d;
    if (i < NN) {
        rowptr[i] = excl;
        cursor[i] = excl;
        if (i == NN - 1) rowptr[NN] = excl + d;
    }
}

__global__ void scatter_kernel(const int* __restrict__ dst, const int* __restrict__ src,
                               int* __restrict__ cursor, int2* __restrict__ edge2) {
    int e = blockIdx.x * blockDim.x + threadIdx.x;
    if (e < NE) {
        int p = atomicAdd(&cursor[dst[e]], 1);
        edge2[p] = make_int2(src[e], e);
    }
}

// ---------------- fused GATv2: logits + online softmax + aggregate -----------
template<int MEAN>
__global__ void gat_fused(const __half* __restrict__ xl, const __half* __restrict__ xr,
                          const __half* __restrict__ em, const int2* __restrict__ edge2,
                          const int* __restrict__ rowptr, const float* __restrict__ att,
                          float* __restrict__ out) {
    const int lane = threadIdx.x & 31;
    const int d = blockIdx.x * (blockDim.x >> 5) + (threadIdx.x >> 5);
    if (d >= NN) return;
    const int start = rowptr[d];
    const int deg = rowptr[d + 1] - start;
    const int c0 = lane * 8;

    if (deg == 0) {
        if (MEAN) {
            if (lane < 8) {
                *(float4*)(out + (size_t)d * 64 + c0) = make_float4(0.f, 0.f, 0.f, 0.f);
                *(float4*)(out + (size_t)d * 64 + c0 + 4) = make_float4(0.f, 0.f, 0.f, 0.f);
            }
        } else {
            *(float4*)(out + (size_t)d * 256 + c0) = make_float4(0.f, 0.f, 0.f, 0.f);
            *(float4*)(out + (size_t)d * 256 + c0 + 4) = make_float4(0.f, 0.f, 0.f, 0.f);
        }
        return;
    }

    float attv[8], xrv[8];
    *(float4*)&attv[0] = *(const float4*)(att + c0);
    *(float4*)&attv[4] = *(const float4*)(att + c0 + 4);
    {
        uint4 ux = *(const uint4*)(xr + (size_t)d * 256 + c0);
        const __half2* hp = (const __half2*)&ux;
#pragma unroll
        for (int q = 0; q < 4; q++) {
            float2 fv = __half22float2(hp[q]);
            xrv[2 * q] = fv.x; xrv[2 * q + 1] = fv.y;
        }
    }

    float m = -INFINITY, s = 0.f;
    float acc[8];
#pragma unroll
    for (int i = 0; i < 8; i++) acc[i] = 0.f;

    int k = 0;
    for (; k + 4 <= deg; k += 4) {
        const int idx = start + k;
        int2 ei[4];
#pragma unroll
        for (int j = 0; j < 4; j++) ei[j] = edge2[idx + j];
        uint4 ux[4], u[4];
#pragma unroll
        for (int j = 0; j < 4; j++) {
            ux[j] = *(const uint4*)(xl + (size_t)ei[j].x * 256 + c0);
            u[j] = ldcs_u4(em + (size_t)ei[j].y * 256 + c0);
        }
        float xv[4][8];
        float h[4];
#pragma unroll
        for (int j = 0; j < 4; j++) {
            const __half2* xp = (const __half2*)&ux[j];
            const __half2* hp = (const __half2*)&u[j];
            float hj = 0.f;
#pragma unroll
            for (int q = 0; q < 4; q++) {
                float2 fx = __half22float2(xp[q]);
                float2 fe = __half22float2(hp[q]);
                xv[j][2 * q] = fx.x; xv[j][2 * q + 1] = fx.y;
                float z0 = fx.x + xrv[2 * q] + fe.x;
                float z1 = fx.y + xrv[2 * q + 1] + fe.y;
                z0 = (z0 > 0.f) ? z0 : 0.2f * z0;
                z1 = (z1 > 0.f) ? z1 : 0.2f * z1;
                hj = fmaf(z0, attv[2 * q], hj);
                hj = fmaf(z1, attv[2 * q + 1], hj);
            }
            h[j] = hj;
        }
#pragma unroll
        for (int o = 1; o <= 4; o <<= 1)
#pragma unroll
            for (int j = 0; j < 4; j++) h[j] += __shfl_xor_sync(0xffffffffu, h[j], o);
        float mn = fmaxf(fmaxf(m, fmaxf(h[0], h[1])), fmaxf(h[2], h[3]));
        float cs = __expf(m - mn);
        float w0 = __expf(h[0] - mn), w1 = __expf(h[1] - mn);
        float w2 = __expf(h[2] - mn), w3 = __expf(h[3] - mn);
        s = s * cs + w0 + w1 + w2 + w3;
#pragma unroll
        for (int i = 0; i < 8; i++)
            acc[i] = fmaf(acc[i], cs,
                          fmaf(w0, xv[0][i], fmaf(w1, xv[1][i],
                               fmaf(w2, xv[2][i], w3 * xv[3][i]))));
        m = mn;
    }
    for (; k < deg; k++) {
        const int2 ei = edge2[start + k];
        uint4 ux = *(const uint4*)(xl + (size_t)ei.x * 256 + c0);
        uint4 ua = ldcs_u4(em + (size_t)ei.y * 256 + c0);
        const __half2* xp = (const __half2*)&ux;
        const __half2* hp = (const __half2*)&ua;
        float xva[8];
        float ha = 0.f;
#pragma unroll
        for (int q = 0; q < 4; q++) {
            float2 fx = __half22float2(xp[q]);
            float2 fe = __half22float2(hp[q]);
            xva[2 * q] = fx.x; xva[2 * q + 1] = fx.y;
            float z0 = fx.x + xrv[2 * q] + fe.x;
            float z1 = fx.y + xrv[2 * q + 1] + fe.y;
            z0 = (z0 > 0.f) ? z0 : 0.2f * z0;
            z1 = (z1 > 0.f) ? z1 : 0.2f * z1;
            ha = fmaf(z0, attv[2 * q], ha);
            ha = fmaf(z1, attv[2 * q + 1], ha);
        }
        ha += __shfl_xor_sync(0xffffffffu, ha, 1);
        ha += __shfl_xor_sync(0xffffffffu, ha, 2);
        ha += __shfl_xor_sync(0xffffffffu, ha, 4);
        float mn = fmaxf(m, ha);
        float cs = __expf(m - mn);
        float wa = __expf(ha - mn);
        s = s * cs + wa;
#pragma unroll
        for (int i = 0; i < 8; i++)
            acc[i] = fmaf(acc[i], cs, wa * xva[i]);
        m = mn;
    }

    const float inv = 1.f / (s + 1e-16f);
    if (MEAN) {
        float v[8];
#pragma unroll
        for (int i = 0; i < 8; i++) {
            float t = acc[i] * inv;
            t += __shfl_xor_sync(0xffffffffu, t, 8);
            t += __shfl_xor_sync(0xffffffffu, t, 16);
            v[i] = 0.25f * t;
        }
        if (lane < 8) {
            *(float4*)(out + (size_t)d * 64 + c0) = *(float4*)&v[0];
            *(float4*)(out + (size_t)d * 64 + c0 + 4) = *(float4*)&v[4];
        }
    } else {
        float v[8];
#pragma unroll
        for (int i = 0; i < 8; i++) v[i] = acc[i] * inv;
        *(float4*)(out + (size_t)d * 256 + c0) = *(float4*)&v[0];
        *(float4*)(out + (size_t)d * 256 + c0 + 4) = *(float4*)&v[4];
    }
}

// ---------------- batch norm ----------------------------------------------------
__global__ void bn_stats(const float* __restrict__ h, double* __restrict__ sum,
                         double* __restrict__ sumsq, int N, int Cf, int rowsPerBlock) {
    const int t = threadIdx.x;
    const int col = t % Cf;
    const int rpb = blockDim.x / Cf;
    int r0 = blockIdx.x * rowsPerBlock;
    int rend = min(N, r0 + rowsPerBlock);
    double s = 0.0, ss = 0.0;
    for (int r = r0 + t / Cf; r < rend; r += rpb) {
        double v = (double)h[(size_t)r * Cf + col];
        s += v;
        ss += v * v;
    }
    atomicAdd(&sum[col], s);
    atomicAdd(&sumsq[col], ss);
}

__global__ void bn_finalize(const double* __restrict__ sum, const double* __restrict__ sumsq,
                            const float* __restrict__ gamma, const float* __restrict__ beta,
                            float* __restrict__ scale, float* __restrict__ shift,
                            int N, int Cf) {
    int c = threadIdx.x;
    if (c >= Cf) return;
    float mu = (float)(sum[c] / N);
    float var = (float)(sumsq[c] / N) - mu * mu;
    float sc = gamma[c] * rsqrtf(var + BN_EPS);
    scale[c] = sc;
    shift[c] = beta[c] - mu * sc;
}

// ---------------- pool (with fused BN) + MLP -------------------------------------
__global__ void pool_kernel(const float* __restrict__ h, const int* __restrict__ batch,
                            const float* __restrict__ scale, const float* __restrict__ shift,
                            float* __restrict__ pooled, float* __restrict__ cnt, int N) {
    int i = blockIdx.x * blockDim.x + threadIdx.x;
    if (i >= N * 64) return;
    int n = i >> 6, c = i & 63;
    int b = batch[n];
    atomicAdd(&pooled[b * 64 + c], h[i] * scale[c] + shift[c]);
    if (c == 0) atomicAdd(&cnt[b], 1.f);
}

__global__ void mlp_kernel(const float* __restrict__ pooled, const float* __restrict__ cnt,
                           const float* __restrict__ Wm1, const float* __restrict__ bm1,
                           const float* __restrict__ Wm2, const float* __restrict__ bm2,
                           const float* __restrict__ Wm3, const float* __restrict__ bm3,
                           float* __restrict__ out) {
    __shared__ float w1[64 * 32], w2[32 * 16], w3[16];
    int t = threadIdx.x;
    for (int i = t; i < 64 * 32; i += 256) w1[i] = Wm1[i];
    for (int i = t; i < 32 * 16; i += 256) w2[i] = Wm2[i];
    if (t < 16) w3[t] = Wm3[t];
    __syncthreads();
    float p[64];
    float c = fmaxf(cnt[t], 1.f);
#pragma unroll
    for (int f = 0; f < 64; f++) p[f] = pooled[t * 64 + f] / c;
    float z1[32];
#pragma unroll
    for (int j = 0; j < 32; j++) {
        float v = bm1[j];
#pragma unroll
        for (int f = 0; f < 64; f++) v = fmaf(p[f], w1[f * 32 + j], v);
        z1[j] = fmaxf(v, 0.f);
    }
    float z2[16];
#pragma unroll
    for (int j = 0; j < 16; j++) {
        float v = bm2[j];
#pragma unroll
        for (int f = 0; f < 32; f++) v = fmaf(z1[f], w2[f * 16 + j], v);
        z2[j] = fmaxf(v, 0.f);
    }
    float o = bm3[0];
#pragma unroll
    for (int f = 0; f < 16; f++) o = fmaf(z2[f], w3[f], o);
    out[t] = o;
}

// ---------------- launch ----------------------------------------------------------
extern "C" void kernel_launch(void* const* d_in, const int* in_sizes, int n_in,
                              void* d_out, int out_size) {
    const float* f[28];
    int nf = 0, idx_ei = -1, idx_b = -1;
    for (int i = 0; i < n_in; i++) {
        if (idx_ei < 0 && in_sizes[i] == 2 * NE) { idx_ei = i; continue; }
        if (idx_b < 0 && in_sizes[i] == NN) { idx_b = i; continue; }
        if (nf < 28) f[nf++] = (const float*)d_in[i];
    }
    const float *x = f[0], *edge_attr = f[1], *W_in = f[2], *b_in = f[3];
    const float *Wl0 = f[4], *bl0 = f[5], *Wr0 = f[6], *br0 = f[7], *We0 = f[8];
    const float *att0 = f[9] /* bias0=f[10] cancels in BN */, *g0 = f[11], *beta0 = f[12];
    const float *Wl1 = f[13], *bl1 = f[14], *Wr1 = f[15], *br1 = f[16], *We1 = f[17];
    const float *att1 = f[18] /* bias1=f[19] cancels in BN */, *g1 = f[20], *beta1 = f[21];
    const float *Wm1 = f[22], *bm1 = f[23], *Wm2 = f[24], *bm2 = f[25], *Wm3 = f[26], *bm3 = f[27];
    const int* edge_index = (const int*)d_in[idx_ei];
    const int* src = edge_index;
    const int* dst = edge_index + NE;
    const int* batch = (const int*)d_in[idx_b];
    float* out = (float*)d_out;

    void *p_agg, *p_h0h, *p_h0l, *p_aggh, *p_aggl, *p_w0h, *p_w0l, *p_w1h, *p_w1l,
         *p_xl, *p_xr, *p_em, *p_e2, *p_deg, *p_rowptr, *p_cursor,
         *p_bsum, *p_boff, *p_bns, *p_scale, *p_shift, *p_pool, *p_cnt;
    cudaGetSymbolAddress(&p_agg, g_agg);
    cudaGetSymbolAddress(&p_h0h, g_h0h);
    cudaGetSymbolAddress(&p_h0l, g_h0l);
    cudaGetSymbolAddress(&p_aggh, g_aggh);
    cudaGetSymbolAddress(&p_aggl, g_aggl);
    cudaGetSymbolAddress(&p_w0h, g_w0h);
    cudaGetSymbolAddress(&p_w0l, g_w0l);
    cudaGetSymbolAddress(&p_w1h, g_w1h);
    cudaGetSymbolAddress(&p_w1l, g_w1l);
    cudaGetSymbolAddress(&p_xl, g_xl);
    cudaGetSymbolAddress(&p_xr, g_xr);
    cudaGetSymbolAddress(&p_em, g_em);
    cudaGetSymbolAddress(&p_e2, g_edge2);
    cudaGetSymbolAddress(&p_deg, g_deg);
    cudaGetSymbolAddress(&p_rowptr, g_rowptr);
    cudaGetSymbolAddress(&p_cursor, g_cursor);
    cudaGetSymbolAddress(&p_bsum, g_bsum);
    cudaGetSymbolAddress(&p_boff, g_boff);
    cudaGetSymbolAddress(&p_bns, g_bns);
    cudaGetSymbolAddress(&p_scale, g_scale);
    cudaGetSymbolAddress(&p_shift, g_shift);
    cudaGetSymbolAddress(&p_pool, g_pool);
    cudaGetSymbolAddress(&p_cnt, g_cnt);
    float* agg = (float*)p_agg;
    unsigned short* h0h = (unsigned short*)p_h0h;
    unsigned short* h0l = (unsigned short*)p_h0l;
    unsigned short* aggh = (unsigned short*)p_aggh;
    unsigned short* aggl = (unsigned short*)p_aggl;
    unsigned short* w0h = (unsigned short*)p_w0h;
    unsigned short* w0l = (unsigned short*)p_w0l;
    unsigned short* w1h = (unsigned short*)p_w1h;
    unsigned short* w1l = (unsigned short*)p_w1l;
    __half* xl = (__half*)p_xl;
    __half* xr = (__half*)p_xr;
    __half* em = (__half*)p_em;
    int2* edge2 = (int2*)p_e2;
    int* deg = (int*)p_deg;
    int* rowptr = (int*)p_rowptr;
    int* cursor = (int*)p_cursor;
    int* bsum = (int*)p_bsum;
    int* boff = (int*)p_boff;
    double* bns = (double*)p_bns;
    double* bnss = bns + 256;
    float* scale = (float*)p_scale;
    float* shift = (float*)p_shift;
    float* pool = (float*)p_pool;
    float* cnt = (float*)p_cnt;

    const int NB = (NN + 7) / 8;
    const int ROWS = 128;
    const int bnBlocks = (NN + ROWS - 1) / ROWS;
    const int MY = (NN + 127) / 128;   // 391
    const int EY = (NE + 127) / 128;   // 4688

    cudaMemsetAsync(deg, 0, NN * sizeof(int));

    // (1,2) pre-split weights
    presplit_w<<<(2 * 64 * 256 + 255) / 256, 256>>>(Wl0, Wr0, w0h, w0l, 64 * 256, 2 * 64 * 256);
    presplit_w<<<(2 * 256 * 256 + 255) / 256, 256>>>(Wl1, Wr1, w1h, w1l, 256 * 256, 2 * 256 * 256);
    // (3) projection
    proj_gemm<<<dim3(1, MY), 256>>>(x, W_in, b_in, h0h, h0l, NN, 64, 64);
    // (4) layer-0 xl|xr double-buffered GEMM  <-- profiled launch
    tgemm_pre<<<dim3(8, MY), 256>>>(h0h, h0l, w0h, w0l, w0h + 64 * 256, w0l + 64 * 256,
                                    bl0, br0, xl, xr, NN, 256, 64);
    // (5) layer-0 em GEMM
    em_gemm<<<dim3(4, EY), 256>>>(edge_attr, We0, em, NE);
    // (6..9) CSR
    hist_kernel<<<(NE + 255) / 256, 256>>>(dst, deg);
    scan_block_sums<<<SNB, SB>>>(deg, bsum);
    scan_offsets<<<1, SB>>>(bsum, boff, SNB);
    scan_final<<<SNB, SB>>>(deg, boff, rowptr, cursor);
    scatter_kernel<<<(NE + 255) / 256, 256>>>(dst, src, cursor, edge2);

    // ---- GATv2 layer 0
    gat_fused<0><<<NB, 256>>>(xl, xr, em, edge2, rowptr, att0, agg);
    cudaMemsetAsync(bns, 0, 512 * sizeof(double));
    bn_stats<<<bnBlocks, 256>>>(agg, bns, bnss, NN, 256, ROWS);
    bn_finalize<<<1, 256>>>(bns, bnss, g0, beta0, scale, shift, NN, 256);

    // ---- GATv2 layer 1
    presplit_a<<<((NN * 256) + 255) / 256, 256>>>(agg, scale, shift, aggh, aggl, NN * 256);
    tgemm_pre<<<dim3(8, MY), 256>>>(aggh, aggl, w1h, w1l, w1h + 256 * 256, w1l + 256 * 256,
                                    bl1, br1, xl, xr, NN, 256, 256);
    em_gemm<<<dim3(4, EY), 256>>>(edge_attr, We1, em, NE);
    gat_fused<1><<<NB, 256>>>(xl, xr, em, edge2, rowptr, att1, agg);
    cudaMemsetAsync(bns, 0, 512 * sizeof(double));
    bn_stats<<<bnBlocks, 256>>>(agg, bns, bnss, NN, 64, ROWS);
    bn_finalize<<<1, 256>>>(bns, bnss, g1, beta1, scale, shift, NN, 64);

    // ---- global mean pool (BN1 fused) + MLP head
    cudaMemsetAsync(pool, 0, NG * 64 * sizeof(float));
    cudaMemsetAsync(cnt, 0, NG * sizeof(float));
    pool_kernel<<<(NN * 64 + 255) / 256, 256>>>(agg, batch, scale, shift, pool, cnt, NN);
    mlp_kernel<<<1, 256>>>(pool, cnt, Wm1, bm1, Wm2, bm2, Wm3, bm3, out);
}

// round 17
// speedup vs baseline: 1.1038x; 1.1038x over previous
#include <cuda_runtime.h>
#include <cuda_fp16.h>
#include <cuda_bf16.h>
#include <math.h>

#define NN 50000
#define NE 600000
#define NG 256
#define BN_EPS 1e-5f
#define SB 256
#define SNB ((NN + SB - 1) / SB)

// ---------------- scratch (device globals) ----------------------------------
__device__ float  g_agg[(size_t)NN * 256];           // gat0 out; reused (first NN*64) as gat1 out
__device__ unsigned short g_h0h[(size_t)NN * 64];    // proj out, bf16 hi
__device__ unsigned short g_h0l[(size_t)NN * 64];    // proj out, bf16 lo
__device__ unsigned short g_aggh[(size_t)NN * 256];  // BN(agg) bf16 hi
__device__ unsigned short g_aggl[(size_t)NN * 256];  // BN(agg) bf16 lo
__device__ unsigned short g_w0h[2 * 64 * 256], g_w0l[2 * 64 * 256];     // Wl0|Wr0 split
__device__ unsigned short g_w1h[2 * 256 * 256], g_w1l[2 * 256 * 256];   // Wl1|Wr1 split
__device__ __half g_xl[(size_t)NN * 256];
__device__ __half g_xr[(size_t)NN * 256];
__device__ __half g_em[(size_t)NE * 256];
__device__ int    g_src_perm[NE];
__device__ int    g_deg[NN];
__device__ int    g_rowptr[NN + 1];
__device__ int    g_cursor[NN];
__device__ int    g_eidx[NE];
__device__ int    g_bsum[SB];
__device__ int    g_boff[SB];
__device__ double g_bns[512];
__device__ float  g_scale[256];
__device__ float  g_shift[256];
__device__ float  g_pool[NG * 64];
__device__ float  g_cnt[NG];

// ---------------- PTX helpers -------------------------------------------------
__device__ __forceinline__ void mma16816(float* c, const unsigned* a, unsigned b0, unsigned b1) {
    asm volatile(
        "mma.sync.aligned.m16n8k16.row.col.f32.bf16.bf16.f32 "
        "{%0,%1,%2,%3},{%4,%5,%6,%7},{%8,%9},{%0,%1,%2,%3};"
        : "+f"(c[0]), "+f"(c[1]), "+f"(c[2]), "+f"(c[3])
        : "r"(a[0]), "r"(a[1]), "r"(a[2]), "r"(a[3]), "r"(b0), "r"(b1));
}
__device__ __forceinline__ void mma16816f16(float* c, const unsigned* a, unsigned b0, unsigned b1) {
    asm volatile(
        "mma.sync.aligned.m16n8k16.row.col.f32.f16.f16.f32 "
        "{%0,%1,%2,%3},{%4,%5,%6,%7},{%8,%9},{%0,%1,%2,%3};"
        : "+f"(c[0]), "+f"(c[1]), "+f"(c[2]), "+f"(c[3])
        : "r"(a[0]), "r"(a[1]), "r"(a[2]), "r"(a[3]), "r"(b0), "r"(b1));
}
__device__ __forceinline__ void ldsm4(unsigned* r, unsigned addr) {
    asm volatile("ldmatrix.sync.aligned.m8n8.x4.shared.b16 {%0,%1,%2,%3}, [%4];"
                 : "=r"(r[0]), "=r"(r[1]), "=r"(r[2]), "=r"(r[3]) : "r"(addr));
}
__device__ __forceinline__ void ldsm4t(unsigned* r, unsigned addr) {
    asm volatile("ldmatrix.sync.aligned.m8n8.x4.trans.shared.b16 {%0,%1,%2,%3}, [%4];"
                 : "=r"(r[0]), "=r"(r[1]), "=r"(r[2]), "=r"(r[3]) : "r"(addr));
}
__device__ __forceinline__ void split_bf16(float v, unsigned short& h, unsigned short& l) {
    __nv_bfloat16 hb = __float2bfloat16(v);
    h = __bfloat16_as_ushort(hb);
    l = __bfloat16_as_ushort(__float2bfloat16(v - __bfloat162float(hb)));
}
__device__ __forceinline__ uint4 ldcs_u4(const void* p) {
    uint4 v;
    asm volatile("ld.global.cs.v4.u32 {%0,%1,%2,%3}, [%4];"
                 : "=r"(v.x), "=r"(v.y), "=r"(v.z), "=r"(v.w) : "l"(p));
    return v;
}
__device__ __forceinline__ void stcs_u4(void* p, uint4 v) {
    asm volatile("st.global.cs.v4.u32 [%0], {%1,%2,%3,%4};"
                 :: "l"(p), "r"(v.x), "r"(v.y), "r"(v.z), "r"(v.w) : "memory");
}

// ---------------- presplit helpers ---------------------------------------------
__global__ void presplit_w(const float* __restrict__ W0, const float* __restrict__ W1,
                           unsigned short* __restrict__ outh, unsigned short* __restrict__ outl,
                           int n0, int ntot) {
    int i = blockIdx.x * blockDim.x + threadIdx.x;
    if (i >= ntot) return;
    float v = (i < n0) ? W0[i] : W1[i - n0];
    unsigned short h, l;
    split_bf16(v, h, l);
    outh[i] = h;
    outl[i] = l;
}

__global__ void presplit_a(const float* __restrict__ A, const float* __restrict__ scale,
                           const float* __restrict__ shift, unsigned short* __restrict__ outh,
                           unsigned short* __restrict__ outl, int total) {
    int i = blockIdx.x * blockDim.x + threadIdx.x;
    if (i >= total) return;
    int c = i & 255;
    float v = fmaxf(A[i] * scale[c] + shift[c], 0.f);
    unsigned short h, l;
    split_bf16(v, h, l);
    outh[i] = h;
    outl[i] = l;
}

// ---------------- slim em GEMM: C[M,256](fp16) = A[M,16] @ B[16,256] ----------
__global__ __launch_bounds__(256) void em_gemm(const float* __restrict__ A,
                                               const float* __restrict__ B,
                                               __half* __restrict__ C, int M) {
    __shared__ __align__(16) unsigned SMU[5120];
    __half* As = (__half*)SMU;
    __half* Bs = (__half*)(SMU + 2048);
    const int t = threadIdx.x;
    const int lane = t & 31, wid = t >> 5;
    const int m0 = blockIdx.y * 128, n0 = blockIdx.x * 64;
    const int wm = (wid & 3) * 32, wn = (wid >> 2) * 32;
    const int N = 256;

    {
        int row = t >> 1, kc = (t & 1) * 8;
        float4 v0 = make_float4(0.f, 0.f, 0.f, 0.f), v1 = v0;
        if (m0 + row < M) {
            const float* p = A + (size_t)(m0 + row) * 16 + kc;
            v0 = *(const float4*)p;
            v1 = *(const float4*)(p + 4);
        }
        __half2 h0 = __floats2half2_rn(v0.x, v0.y);
        __half2 h1 = __floats2half2_rn(v0.z, v0.w);
        __half2 h2 = __floats2half2_rn(v1.x, v1.y);
        __half2 h3 = __floats2half2_rn(v1.z, v1.w);
        int chunk = kc >> 3;
        int pos = row * 32 + ((chunk ^ ((row >> 1) & 3)) << 3);
        *(uint4*)&As[pos] = make_uint4(*(unsigned*)&h0, *(unsigned*)&h1,
                                       *(unsigned*)&h2, *(unsigned*)&h3);
    }
    {
        int k = t >> 4, nc = (t & 15) * 4;
        float4 v = *(const float4*)(B + (size_t)k * N + n0 + nc);
        __half2 h0 = __floats2half2_rn(v.x, v.y);
        __half2 h1 = __floats2half2_rn(v.z, v.w);
        int chunk = nc >> 3;
        int pos = k * 64 + (((chunk ^ (k & 7)) << 3) | (nc & 7));
        *(uint2*)&Bs[pos] = make_uint2(*(unsigned*)&h0, *(unsigned*)&h1);
    }
    __syncthreads();

    float acc[2][4][4];
#pragma unroll
    for (int i = 0; i < 2; i++)
#pragma unroll
        for (int j = 0; j < 4; j++)
#pragma unroll
            for (int q = 0; q < 4; q++) acc[i][j][q] = 0.f;

    const unsigned as_base = (unsigned)__cvta_generic_to_shared(As);
    const unsigned bs_base = (unsigned)__cvta_generic_to_shared(Bs);

    unsigned af[2][4];
#pragma unroll
    for (int mt = 0; mt < 2; mt++) {
        int row = wm + mt * 16 + (lane & 15);
        int chunk = lane >> 4;
        unsigned off = (unsigned)(row * 32 + ((chunk ^ ((row >> 1) & 3)) << 3)) * 2u;
        ldsm4(af[mt], as_base + off);
    }
    unsigned bf[2][4];
    {
        int g = lane >> 3, r = lane & 7;
        int bk = ((g & 1) << 3) + r;
#pragma unroll
        for (int np = 0; np < 2; np++) {
            int n = wn + np * 16 + ((g >> 1) << 3);
            int chunk = n >> 3;
            unsigned off = (unsigned)(bk * 64 + ((chunk ^ (bk & 7)) << 3)) * 2u;
            ldsm4t(bf[np], bs_base + off);
        }
    }
#pragma unroll
    for (int mt = 0; mt < 2; mt++)
#pragma unroll
        for (int nt = 0; nt < 4; nt++) {
            int np = nt >> 1, hf = (nt & 1) << 1;
            mma16816f16(acc[mt][nt], af[mt], bf[np][hf], bf[np][hf + 1]);
        }
    __syncthreads();

    const int r_ = lane >> 2, c2 = (lane & 3) * 2;
    unsigned* stage = SMU + wid * 640;
#pragma unroll
    for (int mt = 0; mt < 2; mt++)
#pragma unroll
        for (int nt = 0; nt < 4; nt++) {
            int colp = nt * 4 + (c2 >> 1);
#pragma unroll
            for (int half = 0; half < 2; half++) {
                int row = mt * 16 + half * 8 + r_;
                __half2 hv = __floats2half2_rn(acc[mt][nt][half * 2],
                                               acc[mt][nt][half * 2 + 1]);
                stage[row * 20 + colp] = *reinterpret_cast<unsigned*>(&hv);
            }
        }
    __syncwarp();
#pragma unroll
    for (int rg = 0; rg < 4; rg++) {
        int row = rg * 8 + (lane >> 2);
        int grow = m0 + wm + row;
        if (grow < M) {
            uint4 v = *(uint4*)&stage[row * 20 + (lane & 3) * 4];
            stcs_u4(C + (size_t)grow * N + n0 + wn + (lane & 3) * 8, v);
        }
    }
}

// ---------------- pre-split bf16 dual-B GEMM ------------------------------------
// C(fp16) = A@B + bias, A given as (Ah,Al) bf16 [M,K] row-major, B as bf16 [K,N].
// Block 128x64, 256 threads, BK=32, reg prefetch. Dual-B: grid.x = 2*(N/64).
__global__ __launch_bounds__(256) void tgemm_pre(
    const unsigned short* __restrict__ Ah, const unsigned short* __restrict__ Al,
    const unsigned short* __restrict__ B0h, const unsigned short* __restrict__ B0l,
    const unsigned short* __restrict__ B1h, const unsigned short* __restrict__ B1l,
    const float* __restrict__ bias0, const float* __restrict__ bias1,
    __half* __restrict__ C0, __half* __restrict__ C1, int M, int N, int K) {
    __shared__ __align__(16) unsigned short SM[12288];
    unsigned short* Ash = SM;
    unsigned short* Asl = SM + 4096;
    unsigned short* Bsh = SM + 8192;
    unsigned short* Bsl = SM + 10240;
    const int t = threadIdx.x;
    const int lane = t & 31, wid = t >> 5;
    const int nb = N >> 6;
    const int bx = blockIdx.x;
    const bool second = bx >= nb;
    const unsigned short* Bh = second ? B1h : B0h;
    const unsigned short* Bl = second ? B1l : B0l;
    const float* bias = second ? bias1 : bias0;
    __half* C = second ? C1 : C0;
    const int m0 = blockIdx.y * 128;
    const int n0 = (second ? bx - nb : bx) * 64;
    const int wm = (wid & 3) * 32, wn = (wid >> 2) * 32;

    float acc[2][4][4];
#pragma unroll
    for (int i = 0; i < 2; i++)
#pragma unroll
        for (int j = 0; j < 4; j++)
#pragma unroll
            for (int q = 0; q < 4; q++) acc[i][j][q] = 0.f;

    const unsigned ah_base = (unsigned)__cvta_generic_to_shared(Ash);
    const unsigned al_base = (unsigned)__cvta_generic_to_shared(Asl);
    const unsigned bh_base = (unsigned)__cvta_generic_to_shared(Bsh);
    const unsigned bl_base = (unsigned)__cvta_generic_to_shared(Bsl);

    uint4 pah[2], pal[2], pbh, pbl;
    {
#pragma unroll
        for (int i = 0; i < 2; i++) {
            int fidx = t + i * 256;
            int row = fidx >> 2, kc8 = (fidx & 3) << 3;
            pah[i] = make_uint4(0, 0, 0, 0);
            pal[i] = make_uint4(0, 0, 0, 0);
            if (m0 + row < M) {
                pah[i] = *(const uint4*)(Ah + (size_t)(m0 + row) * K + kc8);
                pal[i] = *(const uint4*)(Al + (size_t)(m0 + row) * K + kc8);
            }
        }
        int k = t >> 3, nc8 = (t & 7) << 3;
        pbh = *(const uint4*)(Bh + (size_t)k * N + n0 + nc8);
        pbl = *(const uint4*)(Bl + (size_t)k * N + n0 + nc8);
    }

    for (int k0 = 0; k0 < K; k0 += 32) {
#pragma unroll
        for (int i = 0; i < 2; i++) {
            int fidx = t + i * 256;
            int row = fidx >> 2, kc8 = (fidx & 3) << 3;
            int chunk = kc8 >> 3;
            int pos = row * 32 + ((chunk ^ ((row >> 1) & 3)) << 3);
            *(uint4*)&Ash[pos] = pah[i];
            *(uint4*)&Asl[pos] = pal[i];
        }
        {
            int k = t >> 3, nc8 = (t & 7) << 3;
            int chunk = nc8 >> 3;
            int pos = k * 64 + ((chunk ^ (k & 7)) << 3);
            *(uint4*)&Bsh[pos] = pbh;
            *(uint4*)&Bsl[pos] = pbl;
        }
        __syncthreads();

        int kn = k0 + 32;
        if (kn < K) {
#pragma unroll
            for (int i = 0; i < 2; i++) {
                int fidx = t + i * 256;
                int row = fidx >> 2, kc8 = (fidx & 3) << 3;
                pah[i] = make_uint4(0, 0, 0, 0);
                pal[i] = make_uint4(0, 0, 0, 0);
                if (m0 + row < M) {
                    pah[i] = *(const uint4*)(Ah + (size_t)(m0 + row) * K + kn + kc8);
                    pal[i] = *(const uint4*)(Al + (size_t)(m0 + row) * K + kn + kc8);
                }
            }
            int k = t >> 3, nc8 = (t & 7) << 3;
            pbh = *(const uint4*)(Bh + (size_t)(kn + k) * N + n0 + nc8);
            pbl = *(const uint4*)(Bl + (size_t)(kn + k) * N + n0 + nc8);
        }

#pragma unroll
        for (int kk = 0; kk < 32; kk += 16) {
            unsigned afh[2][4], afl[2][4];
#pragma unroll
            for (int mt = 0; mt < 2; mt++) {
                int row = wm + mt * 16 + (lane & 15);
                int chunk = (kk >> 3) + (lane >> 4);
                unsigned off = (unsigned)(row * 32 + ((chunk ^ ((row >> 1) & 3)) << 3)) * 2u;
                ldsm4(afh[mt], ah_base + off);
                ldsm4(afl[mt], al_base + off);
            }
            unsigned bfh[2][4], bfl[2][4];
            int g = lane >> 3, r = lane & 7;
            int bk = kk + ((g & 1) << 3) + r;
#pragma unroll
            for (int np = 0; np < 2; np++) {
                int n = wn + np * 16 + ((g >> 1) << 3);
                int chunk = n >> 3;
                unsigned off = (unsigned)(bk * 64 + ((chunk ^ (bk & 7)) << 3)) * 2u;
                ldsm4t(bfh[np], bh_base + off);
                ldsm4t(bfl[np], bl_base + off);
            }
#pragma unroll
            for (int mt = 0; mt < 2; mt++)
#pragma unroll
                for (int nt = 0; nt < 4; nt++) {
                    int np = nt >> 1, hf = (nt & 1) << 1;
                    mma16816(acc[mt][nt], afh[mt], bfh[np][hf], bfh[np][hf + 1]);
                    mma16816(acc[mt][nt], afh[mt], bfl[np][hf], bfl[np][hf + 1]);
                    mma16816(acc[mt][nt], afl[mt], bfh[np][hf], bfh[np][hf + 1]);
                }
        }
        __syncthreads();
    }

    // staged fp16 epilogue
    const int r_ = lane >> 2, c2 = (lane & 3) * 2;
    unsigned* stage = (unsigned*)SM + wid * 640;
#pragma unroll
    for (int mt = 0; mt < 2; mt++)
#pragma unroll
        for (int nt = 0; nt < 4; nt++) {
            int colp = nt * 4 + (c2 >> 1);
            int col = n0 + wn + nt * 8 + c2;
#pragma unroll
            for (int half = 0; half < 2; half++) {
                int row = mt * 16 + half * 8 + r_;
                float v0 = acc[mt][nt][half * 2] + bias[col];
                float v1 = acc[mt][nt][half * 2 + 1] + bias[col + 1];
                __half2 hv = __floats2half2_rn(v0, v1);
                stage[row * 20 + colp] = *reinterpret_cast<unsigned*>(&hv);
            }
        }
    __syncwarp();
#pragma unroll
    for (int rg = 0; rg < 4; rg++) {
        int row = rg * 8 + (lane >> 2);
        int grow = m0 + wm + row;
        if (grow < M) {
            uint4 v = *(uint4*)&stage[row * 20 + (lane & 3) * 4];
            stcs_u4(C + (size_t)grow * N + n0 + wn + (lane & 3) * 8, v);
        }
    }
}

// ---------------- projection GEMM (fp32 in, bf16 hi/lo split out) ---------------
__global__ __launch_bounds__(256) void proj_gemm(const float* __restrict__ A,
                                                 const float* __restrict__ B,
                                                 const float* __restrict__ bias,
                                                 unsigned short* __restrict__ Ch,
                                                 unsigned short* __restrict__ Cl,
                                                 int M, int N, int K) {
    __shared__ __align__(16) unsigned short SM[12288];
    unsigned short* Ash = SM;
    unsigned short* Asl = SM + 4096;
    unsigned short* Bsh = SM + 8192;
    unsigned short* Bsl = SM + 10240;
    const int t = threadIdx.x;
    const int lane = t & 31, wid = t >> 5;
    const int m0 = blockIdx.y * 128;
    const int n0 = blockIdx.x * 64;
    const int wm = (wid & 3) * 32, wn = (wid >> 2) * 32;

    float acc[2][4][4];
#pragma unroll
    for (int i = 0; i < 2; i++)
#pragma unroll
        for (int j = 0; j < 4; j++)
#pragma unroll
            for (int q = 0; q < 4; q++) acc[i][j][q] = 0.f;

    const unsigned ah_base = (unsigned)__cvta_generic_to_shared(Ash);
    const unsigned al_base = (unsigned)__cvta_generic_to_shared(Asl);
    const unsigned bh_base = (unsigned)__cvta_generic_to_shared(Bsh);
    const unsigned bl_base = (unsigned)__cvta_generic_to_shared(Bsl);

    for (int k0 = 0; k0 < K; k0 += 32) {
#pragma unroll
        for (int i = 0; i < 4; i++) {
            int fidx = t + i * 256;
            int row = fidx >> 3, kc = (fidx & 7) << 2;
            float4 v = make_float4(0.f, 0.f, 0.f, 0.f);
            if (m0 + row < M) v = *(const float4*)(A + (size_t)(m0 + row) * K + k0 + kc);
            unsigned short h[4], l[4];
            split_bf16(v.x, h[0], l[0]); split_bf16(v.y, h[1], l[1]);
            split_bf16(v.z, h[2], l[2]); split_bf16(v.w, h[3], l[3]);
            int chunk = kc >> 3;
            int pos = row * 32 + (((chunk ^ ((row >> 1) & 3)) << 3) | (kc & 7));
            *(uint2*)&Ash[pos] = make_uint2((unsigned)h[0] | ((unsigned)h[1] << 16),
                                            (unsigned)h[2] | ((unsigned)h[3] << 16));
            *(uint2*)&Asl[pos] = make_uint2((unsigned)l[0] | ((unsigned)l[1] << 16),
                                            (unsigned)l[2] | ((unsigned)l[3] << 16));
        }
#pragma unroll
        for (int i = 0; i < 2; i++) {
            int fidx = t + i * 256;
            int k = fidx >> 4, nc = (fidx & 15) << 2;
            float4 v = *(const float4*)(B + (size_t)(k0 + k) * N + n0 + nc);
            unsigned short h[4], l[4];
            split_bf16(v.x, h[0], l[0]); split_bf16(v.y, h[1], l[1]);
            split_bf16(v.z, h[2], l[2]); split_bf16(v.w, h[3], l[3]);
            int chunk = nc >> 3;
            int pos = k * 64 + (((chunk ^ (k & 7)) << 3) | (nc & 7));
            *(uint2*)&Bsh[pos] = make_uint2((unsigned)h[0] | ((unsigned)h[1] << 16),
                                            (unsigned)h[2] | ((unsigned)h[3] << 16));
            *(uint2*)&Bsl[pos] = make_uint2((unsigned)l[0] | ((unsigned)l[1] << 16),
                                            (unsigned)l[2] | ((unsigned)l[3] << 16));
        }
        __syncthreads();

#pragma unroll
        for (int kk = 0; kk < 32; kk += 16) {
            unsigned afh[2][4], afl[2][4];
#pragma unroll
            for (int mt = 0; mt < 2; mt++) {
                int row = wm + mt * 16 + (lane & 15);
                int chunk = (kk >> 3) + (lane >> 4);
                unsigned off = (unsigned)(row * 32 + ((chunk ^ ((row >> 1) & 3)) << 3)) * 2u;
                ldsm4(afh[mt], ah_base + off);
                ldsm4(afl[mt], al_base + off);
            }
            unsigned bfh[2][4], bfl[2][4];
            int g = lane >> 3, r = lane & 7;
            int bk = kk + ((g & 1) << 3) + r;
#pragma unroll
            for (int np = 0; np < 2; np++) {
                int n = wn + np * 16 + ((g >> 1) << 3);
                int chunk = n >> 3;
                unsigned off = (unsigned)(bk * 64 + ((chunk ^ (bk & 7)) << 3)) * 2u;
                ldsm4t(bfh[np], bh_base + off);
                ldsm4t(bfl[np], bl_base + off);
            }
#pragma unroll
            for (int mt = 0; mt < 2; mt++)
#pragma unroll
                for (int nt = 0; nt < 4; nt++) {
                    int np = nt >> 1, hf = (nt & 1) << 1;
                    mma16816(acc[mt][nt], afh[mt], bfh[np][hf], bfh[np][hf + 1]);
                    mma16816(acc[mt][nt], afh[mt], bfl[np][hf], bfl[np][hf + 1]);
                    mma16816(acc[mt][nt], afl[mt], bfh[np][hf], bfh[np][hf + 1]);
                }
        }
        __syncthreads();
    }

    const int r_ = lane >> 2, c2 = (lane & 3) * 2;
#pragma unroll
    for (int mt = 0; mt < 2; mt++)
#pragma unroll
        for (int nt = 0; nt < 4; nt++) {
            int col = n0 + wn + nt * 8 + c2;
#pragma unroll
            for (int half = 0; half < 2; half++) {
                int row = m0 + wm + mt * 16 + r_ + half * 8;
                if (row >= M) continue;
                float v0 = fmaxf(acc[mt][nt][half * 2] + bias[col], 0.f);
                float v1 = fmaxf(acc[mt][nt][half * 2 + 1] + bias[col + 1], 0.f);
                unsigned short h0_, l0_, h1_, l1_;
                split_bf16(v0, h0_, l0_);
                split_bf16(v1, h1_, l1_);
                size_t base = (size_t)row * N + col;
                Ch[base] = h0_; Ch[base + 1] = h1_;
                Cl[base] = l0_; Cl[base + 1] = l1_;
            }
        }
}

// ---------------- CSR build --------------------------------------------------
__global__ void hist_kernel(const int* __restrict__ dst, int* __restrict__ deg) {
    int e = blockIdx.x * blockDim.x + threadIdx.x;
    if (e < NE) atomicAdd(&deg[dst[e]], 1);
}

__global__ void scan_block_sums(const int* __restrict__ deg, int* __restrict__ bsum) {
    __shared__ int sh[SB];
    int i = blockIdx.x * SB + threadIdx.x;
    sh[threadIdx.x] = (i < NN) ? deg[i] : 0;
    __syncthreads();
    for (int o = SB / 2; o > 0; o >>= 1) {
        if (threadIdx.x < o) sh[threadIdx.x] += sh[threadIdx.x + o];
        __syncthreads();
    }
    if (threadIdx.x == 0) bsum[blockIdx.x] = sh[0];
}

__global__ void scan_offsets(const int* __restrict__ bsum, int* __restrict__ boff, int nb) {
    __shared__ int sh[SB];
    int t = threadIdx.x;
    int mine = (t < nb) ? bsum[t] : 0;
    sh[t] = mine;
    __syncthreads();
    for (int o = 1; o < SB; o <<= 1) {
        int v = (t >= o) ? sh[t - o] : 0;
        __syncthreads();
        sh[t] += v;
        __syncthreads();
    }
    if (t < nb) boff[t] = sh[t] - mine;
}

__global__ void scan_final(const int* __restrict__ deg, const int* __restrict__ boff,
                           int* __restrict__ rowptr, int* __restrict__ cursor) {
    __shared__ int sh[SB];
    int t = threadIdx.x;
    int i = blockIdx.x * SB + t;
    int d = (i < NN) ? deg[i] : 0;
    sh[t] = d;
    __syncthreads();
    for (int o = 1; o < SB; o <<= 1) {
        int v = (t >= o) ? sh[t - o] : 0;
        __syncthreads();
        sh[t] += v;
        __syncthreads();
    }
    int excl = boff[blockIdx.x] + sh[t] - d;
    if (i < NN) {
        rowptr[i] = excl;
        cursor[i] = excl;
        if (i == NN - 1) rowptr[NN] = excl + d;
    }
}

__global__ void scatter_kernel(const int* __restrict__ dst, const int* __restrict__ src,
                               int* __restrict__ cursor, int* __restrict__ eidx,
                               int* __restrict__ src_perm) {
    int e = blockIdx.x * blockDim.x + threadIdx.x;
    if (e < NE) {
        int p = atomicAdd(&cursor[dst[e]], 1);
        eidx[p] = e;
        src_perm[p] = src[e];
    }
}

// ---------------- fused GATv2: logits + online softmax + aggregate -----------
template<int MEAN>
__global__ void gat_fused(const __half* __restrict__ xl, const __half* __restrict__ xr,
                          const __half* __restrict__ em, const int* __restrict__ src_perm,
                          const int* __restrict__ eidx, const int* __restrict__ rowptr,
                          const float* __restrict__ att, float* __restrict__ out) {
    const int lane = threadIdx.x & 31;
    const int d = blockIdx.x * (blockDim.x >> 5) + (threadIdx.x >> 5);
    if (d >= NN) return;
    const int start = rowptr[d];
    const int deg = rowptr[d + 1] - start;
    const int c0 = lane * 8;

    if (deg == 0) {
        if (MEAN) {
            if (lane < 8) {
                *(float4*)(out + (size_t)d * 64 + c0) = make_float4(0.f, 0.f, 0.f, 0.f);
                *(float4*)(out + (size_t)d * 64 + c0 + 4) = make_float4(0.f, 0.f, 0.f, 0.f);
            }
        } else {
            *(float4*)(out + (size_t)d * 256 + c0) = make_float4(0.f, 0.f, 0.f, 0.f);
            *(float4*)(out + (size_t)d * 256 + c0 + 4) = make_float4(0.f, 0.f, 0.f, 0.f);
        }
        return;
    }

    float attv[8], xrv[8];
    *(float4*)&attv[0] = *(const float4*)(att + c0);
    *(float4*)&attv[4] = *(const float4*)(att + c0 + 4);
    {
        uint4 ux = *(const uint4*)(xr + (size_t)d * 256 + c0);
        const __half2* hp = (const __half2*)&ux;
#pragma unroll
        for (int q = 0; q < 4; q++) {
            float2 fv = __half22float2(hp[q]);
            xrv[2 * q] = fv.x; xrv[2 * q + 1] = fv.y;
        }
    }

    float m = -INFINITY, s = 0.f;
    float acc[8];
#pragma unroll
    for (int i = 0; i < 8; i++) acc[i] = 0.f;

    int k = 0;
    for (; k + 4 <= deg; k += 4) {
        const int idx = start + k;
        int e[4], sn[4];
#pragma unroll
        for (int j = 0; j < 4; j++) { e[j] = eidx[idx + j]; sn[j] = src_perm[idx + j]; }
        uint4 ux[4], u[4];
#pragma unroll
        for (int j = 0; j < 4; j++) {
            ux[j] = *(const uint4*)(xl + (size_t)sn[j] * 256 + c0);
            u[j] = ldcs_u4(em + (size_t)e[j] * 256 + c0);
        }
        float xv[4][8];
        float h[4];
#pragma unroll
        for (int j = 0; j < 4; j++) {
            const __half2* xp = (const __half2*)&ux[j];
            const __half2* hp = (const __half2*)&u[j];
            float hj = 0.f;
#pragma unroll
            for (int q = 0; q < 4; q++) {
                float2 fx = __half22float2(xp[q]);
                float2 fe = __half22float2(hp[q]);
                xv[j][2 * q] = fx.x; xv[j][2 * q + 1] = fx.y;
                float z0 = fx.x + xrv[2 * q] + fe.x;
                float z1 = fx.y + xrv[2 * q + 1] + fe.y;
                z0 = (z0 > 0.f) ? z0 : 0.2f * z0;
                z1 = (z1 > 0.f) ? z1 : 0.2f * z1;
                hj = fmaf(z0, attv[2 * q], hj);
                hj = fmaf(z1, attv[2 * q + 1], hj);
            }
            h[j] = hj;
        }
#pragma unroll
        for (int o = 1; o <= 4; o <<= 1)
#pragma unroll
            for (int j = 0; j < 4; j++) h[j] += __shfl_xor_sync(0xffffffffu, h[j], o);
        float mn = fmaxf(fmaxf(m, fmaxf(h[0], h[1])), fmaxf(h[2], h[3]));
        float cs = __expf(m - mn);
        float w0 = __expf(h[0] - mn), w1 = __expf(h[1] - mn);
        float w2 = __expf(h[2] - mn), w3 = __expf(h[3] - mn);
        s = s * cs + w0 + w1 + w2 + w3;
#pragma unroll
        for (int i = 0; i < 8; i++)
            acc[i] = fmaf(acc[i], cs,
                          fmaf(w0, xv[0][i], fmaf(w1, xv[1][i],
                               fmaf(w2, xv[2][i], w3 * xv[3][i]))));
        m = mn;
    }
    for (; k < deg; k++) {
        const int i0 = start + k;
        const int e0 = eidx[i0];
        const int s0 = src_perm[i0];
        uint4 ux = *(const uint4*)(xl + (size_t)s0 * 256 + c0);
        uint4 ua = ldcs_u4(em + (size_t)e0 * 256 + c0);
        const __half2* xp = (const __half2*)&ux;
        const __half2* hp = (const __half2*)&ua;
        float xva[8];
        float ha = 0.f;
#pragma unroll
        for (int q = 0; q < 4; q++) {
            float2 fx = __half22float2(xp[q]);
            float2 fe = __half22float2(hp[q]);
            xva[2 * q] = fx.x; xva[2 * q + 1] = fx.y;
            float z0 = fx.x + xrv[2 * q] + fe.x;
            float z1 = fx.y + xrv[2 * q + 1] + fe.y;
            z0 = (z0 > 0.f) ? z0 : 0.2f * z0;
            z1 = (z1 > 0.f) ? z1 : 0.2f * z1;
            ha = fmaf(z0, attv[2 * q], ha);
            ha = fmaf(z1, attv[2 * q + 1], ha);
        }
        ha += __shfl_xor_sync(0xffffffffu, ha, 1);
        ha += __shfl_xor_sync(0xffffffffu, ha, 2);
        ha += __shfl_xor_sync(0xffffffffu, ha, 4);
        float mn = fmaxf(m, ha);
        float cs = __expf(m - mn);
        float wa = __expf(ha - mn);
        s = s * cs + wa;
#pragma unroll
        for (int i = 0; i < 8; i++)
            acc[i] = fmaf(acc[i], cs, wa * xva[i]);
        m = mn;
    }

    const float inv = 1.f / (s + 1e-16f);
    if (MEAN) {
        float v[8];
#pragma unroll
        for (int i = 0; i < 8; i++) {
            float t = acc[i] * inv;
            t += __shfl_xor_sync(0xffffffffu, t, 8);
            t += __shfl_xor_sync(0xffffffffu, t, 16);
            v[i] = 0.25f * t;
        }
        if (lane < 8) {
            *(float4*)(out + (size_t)d * 64 + c0) = *(float4*)&v[0];
            *(float4*)(out + (size_t)d * 64 + c0 + 4) = *(float4*)&v[4];
        }
    } else {
        float v[8];
#pragma unroll
        for (int i = 0; i < 8; i++) v[i] = acc[i] * inv;
        *(float4*)(out + (size_t)d * 256 + c0) = *(float4*)&v[0];
        *(float4*)(out + (size_t)d * 256 + c0 + 4) = *(float4*)&v[4];
    }
}

// ---------------- batch norm ----------------------------------------------------
__global__ void bn_stats(const float* __restrict__ h, double* __restrict__ sum,
                         double* __restrict__ sumsq, int N, int Cf, int rowsPerBlock) {
    const int t = threadIdx.x;
    const int col = t % Cf;
    const int rpb = blockDim.x / Cf;
    int r0 = blockIdx.x * rowsPerBlock;
    int rend = min(N, r0 + rowsPerBlock);
    double s = 0.0, ss = 0.0;
    for (int r = r0 + t / Cf; r < rend; r += rpb) {
        double v = (double)h[(size_t)r * Cf + col];
        s += v;
        ss += v * v;
    }
    atomicAdd(&sum[col], s);
    atomicAdd(&sumsq[col], ss);
}

__global__ void bn_finalize(const double* __restrict__ sum, const double* __restrict__ sumsq,
                            const float* __restrict__ gamma, const float* __restrict__ beta,
                            float* __restrict__ scale, float* __restrict__ shift,
                            int N, int Cf) {
    int c = threadIdx.x;
    if (c >= Cf) return;
    float mu = (float)(sum[c] / N);
    float var = (float)(sumsq[c] / N) - mu * mu;
    float sc = gamma[c] * rsqrtf(var + BN_EPS);
    scale[c] = sc;
    shift[c] = beta[c] - mu * sc;
}

// ---------------- pool (with fused BN) + MLP -------------------------------------
__global__ void pool_kernel(const float* __restrict__ h, const int* __restrict__ batch,
                            const float* __restrict__ scale, const float* __restrict__ shift,
                            float* __restrict__ pooled, float* __restrict__ cnt, int N) {
    int i = blockIdx.x * blockDim.x + threadIdx.x;
    if (i >= N * 64) return;
    int n = i >> 6, c = i & 63;
    int b = batch[n];
    atomicAdd(&pooled[b * 64 + c], h[i] * scale[c] + shift[c]);
    if (c == 0) atomicAdd(&cnt[b], 1.f);
}

__global__ void mlp_kernel(const float* __restrict__ pooled, const float* __restrict__ cnt,
                           const float* __restrict__ Wm1, const float* __restrict__ bm1,
                           const float* __restrict__ Wm2, const float* __restrict__ bm2,
                           const float* __restrict__ Wm3, const float* __restrict__ bm3,
                           float* __restrict__ out) {
    __shared__ float w1[64 * 32], w2[32 * 16], w3[16];
    int t = threadIdx.x;
    for (int i = t; i < 64 * 32; i += 256) w1[i] = Wm1[i];
    for (int i = t; i < 32 * 16; i += 256) w2[i] = Wm2[i];
    if (t < 16) w3[t] = Wm3[t];
    __syncthreads();
    float p[64];
    float c = fmaxf(cnt[t], 1.f);
#pragma unroll
    for (int f = 0; f < 64; f++) p[f] = pooled[t * 64 + f] / c;
    float z1[32];
#pragma unroll
    for (int j = 0; j < 32; j++) {
        float v = bm1[j];
#pragma unroll
        for (int f = 0; f < 64; f++) v = fmaf(p[f], w1[f * 32 + j], v);
        z1[j] = fmaxf(v, 0.f);
    }
    float z2[16];
#pragma unroll
    for (int j = 0; j < 16; j++) {
        float v = bm2[j];
#pragma unroll
        for (int f = 0; f < 32; f++) v = fmaf(z1[f], w2[f * 16 + j], v);
        z2[j] = fmaxf(v, 0.f);
    }
    float o = bm3[0];
#pragma unroll
    for (int f = 0; f < 16; f++) o = fmaf(z2[f], w3[f], o);
    out[t] = o;
}

// ---------------- launch ----------------------------------------------------------
extern "C" void kernel_launch(void* const* d_in, const int* in_sizes, int n_in,
                              void* d_out, int out_size) {
    const float* f[28];
    int nf = 0, idx_ei = -1, idx_b = -1;
    for (int i = 0; i < n_in; i++) {
        if (idx_ei < 0 && in_sizes[i] == 2 * NE) { idx_ei = i; continue; }
        if (idx_b < 0 && in_sizes[i] == NN) { idx_b = i; continue; }
        if (nf < 28) f[nf++] = (const float*)d_in[i];
    }
    const float *x = f[0], *edge_attr = f[1], *W_in = f[2], *b_in = f[3];
    const float *Wl0 = f[4], *bl0 = f[5], *Wr0 = f[6], *br0 = f[7], *We0 = f[8];
    const float *att0 = f[9] /* bias0=f[10] cancels in BN */, *g0 = f[11], *beta0 = f[12];
    const float *Wl1 = f[13], *bl1 = f[14], *Wr1 = f[15], *br1 = f[16], *We1 = f[17];
    const float *att1 = f[18] /* bias1=f[19] cancels in BN */, *g1 = f[20], *beta1 = f[21];
    const float *Wm1 = f[22], *bm1 = f[23], *Wm2 = f[24], *bm2 = f[25], *Wm3 = f[26], *bm3 = f[27];
    const int* edge_index = (const int*)d_in[idx_ei];
    const int* src = edge_index;
    const int* dst = edge_index + NE;
    const int* batch = (const int*)d_in[idx_b];
    float* out = (float*)d_out;

    void *p_agg, *p_h0h, *p_h0l, *p_aggh, *p_aggl, *p_w0h, *p_w0l, *p_w1h, *p_w1l,
         *p_xl, *p_xr, *p_em, *p_sp, *p_deg, *p_rowptr, *p_cursor, *p_eidx,
         *p_bsum, *p_boff, *p_bns, *p_scale, *p_shift, *p_pool, *p_cnt;
    cudaGetSymbolAddress(&p_agg, g_agg);
    cudaGetSymbolAddress(&p_h0h, g_h0h);
    cudaGetSymbolAddress(&p_h0l, g_h0l);
    cudaGetSymbolAddress(&p_aggh, g_aggh);
    cudaGetSymbolAddress(&p_aggl, g_aggl);
    cudaGetSymbolAddress(&p_w0h, g_w0h);
    cudaGetSymbolAddress(&p_w0l, g_w0l);
    cudaGetSymbolAddress(&p_w1h, g_w1h);
    cudaGetSymbolAddress(&p_w1l, g_w1l);
    cudaGetSymbolAddress(&p_xl, g_xl);
    cudaGetSymbolAddress(&p_xr, g_xr);
    cudaGetSymbolAddress(&p_em, g_em);
    cudaGetSymbolAddress(&p_sp, g_src_perm);
    cudaGetSymbolAddress(&p_deg, g_deg);
    cudaGetSymbolAddress(&p_rowptr, g_rowptr);
    cudaGetSymbolAddress(&p_cursor, g_cursor);
    cudaGetSymbolAddress(&p_eidx, g_eidx);
    cudaGetSymbolAddress(&p_bsum, g_bsum);
    cudaGetSymbolAddress(&p_boff, g_boff);
    cudaGetSymbolAddress(&p_bns, g_bns);
    cudaGetSymbolAddress(&p_scale, g_scale);
    cudaGetSymbolAddress(&p_shift, g_shift);
    cudaGetSymbolAddress(&p_pool, g_pool);
    cudaGetSymbolAddress(&p_cnt, g_cnt);
    float* agg = (float*)p_agg;
    unsigned short* h0h = (unsigned short*)p_h0h;
    unsigned short* h0l = (unsigned short*)p_h0l;
    unsigned short* aggh = (unsigned short*)p_aggh;
    unsigned short* aggl = (unsigned short*)p_aggl;
    unsigned short* w0h = (unsigned short*)p_w0h;
    unsigned short* w0l = (unsigned short*)p_w0l;
    unsigned short* w1h = (unsigned short*)p_w1h;
    unsigned short* w1l = (unsigned short*)p_w1l;
    __half* xl = (__half*)p_xl;
    __half* xr = (__half*)p_xr;
    __half* em = (__half*)p_em;
    int* src_perm = (int*)p_sp;
    int* deg = (int*)p_deg;
    int* rowptr = (int*)p_rowptr;
    int* cursor = (int*)p_cursor;
    int* eidx = (int*)p_eidx;
    int* bsum = (int*)p_bsum;
    int* boff = (int*)p_boff;
    double* bns = (double*)p_bns;
    double* bnss = bns + 256;
    float* scale = (float*)p_scale;
    float* shift = (float*)p_shift;
    float* pool = (float*)p_pool;
    float* cnt = (float*)p_cnt;

    const int NB = (NN + 7) / 8;
    const int ROWS = 128;
    const int bnBlocks = (NN + ROWS - 1) / ROWS;
    const int MY = (NN + 127) / 128;   // 391
    const int EY = (NE + 127) / 128;   // 4688

    cudaMemsetAsync(deg, 0, NN * sizeof(int));

    // (1,2) pre-split weights (numerics-identical hoist of in-GEMM split)
    presplit_w<<<(2 * 64 * 256 + 255) / 256, 256>>>(Wl0, Wr0, w0h, w0l, 64 * 256, 2 * 64 * 256);
    presplit_w<<<(2 * 256 * 256 + 255) / 256, 256>>>(Wl1, Wr1, w1h, w1l, 256 * 256, 2 * 256 * 256);
    // (3) projection: h0 = relu(x@W_in + b_in), written as bf16 hi/lo pair
    proj_gemm<<<dim3(1, MY), 256>>>(x, W_in, b_in, h0h, h0l, NN, 64, 64);
    // (4) layer-0 xl|xr pre-split GEMM  <-- profiled launch
    tgemm_pre<<<dim3(8, MY), 256>>>(h0h, h0l, w0h, w0l, w0h + 64 * 256, w0l + 64 * 256,
                                    bl0, br0, xl, xr, NN, 256, 64);
    // (5) layer-0 em GEMM
    em_gemm<<<dim3(4, EY), 256>>>(edge_attr, We0, em, NE);
    // (6..9) CSR
    hist_kernel<<<(NE + 255) / 256, 256>>>(dst, deg);
    scan_block_sums<<<SNB, SB>>>(deg, bsum);
    scan_offsets<<<1, SB>>>(bsum, boff, SNB);
    scan_final<<<SNB, SB>>>(deg, boff, rowptr, cursor);
    scatter_kernel<<<(NE + 255) / 256, 256>>>(dst, src, cursor, eidx, src_perm);

    // ---- GATv2 layer 0
    gat_fused<0><<<NB, 256>>>(xl, xr, em, src_perm, eidx, rowptr, att0, agg);
    cudaMemsetAsync(bns, 0, 512 * sizeof(double));
    bn_stats<<<bnBlocks, 256>>>(agg, bns, bnss, NN, 256, ROWS);
    bn_finalize<<<1, 256>>>(bns, bnss, g0, beta0, scale, shift, NN, 256);

    // ---- GATv2 layer 1: BN+relu+split agg, then pre-split GEMM
    presplit_a<<<((NN * 256) + 255) / 256, 256>>>(agg, scale, shift, aggh, aggl, NN * 256);
    tgemm_pre<<<dim3(8, MY), 256>>>(aggh, aggl, w1h, w1l, w1h + 256 * 256, w1l + 256 * 256,
                                    bl1, br1, xl, xr, NN, 256, 256);
    em_gemm<<<dim3(4, EY), 256>>>(edge_attr, We1, em, NE);
    gat_fused<1><<<NB, 256>>>(xl, xr, em, src_perm, eidx, rowptr, att1, agg);  // h2 -> agg[:NN*64]
    cudaMemsetAsync(bns, 0, 512 * sizeof(double));
    bn_stats<<<bnBlocks, 256>>>(agg, bns, bnss, NN, 64, ROWS);
    bn_finalize<<<1, 256>>>(bns, bnss, g1, beta1, scale, shift, NN, 64);

    // ---- global mean pool (BN1 fused) + MLP head
    cudaMemsetAsync(pool, 0, NG * 64 * sizeof(float));
    cudaMemsetAsync(cnt, 0, NG * sizeof(float));
    pool_kernel<<<(NN * 64 + 255) / 256, 256>>>(agg, batch, scale, shift, pool, cnt, NN);
    mlp_kernel<<<1, 256>>>(pool, cnt, Wm1, bm1, Wm2, bm2, Wm3, bm3, out);
}